// round 3
// baseline (speedup 1.0000x reference)
#include <cuda_runtime.h>
#include <cstdint>

#define B_   64
#define T_   1024
#define H_   512
#define I_   64
#define O_   8
#define ALPHA 0.2f
#define NSTD  0.05f

#define CL    8                 // cluster size (column tiles per batch group)
#define NBG   16                // batch groups (clusters)
#define GRID  (CL*NBG)          // 128 CTAs, single wave
#define TPB   512
#define NB    4                 // batches per cluster
#define NC    64                // columns per CTA
#define KTOT  (H_+I_)           // 576
#define KS    8                 // k-slices
#define NPAIR 36                // k-pairs per thread: (64 wrec + 8 wi)/2

// ---- packed f32x2 helpers (sm_100+) ----
__device__ __forceinline__ unsigned long long pk2(float lo, float hi) {
    unsigned long long v;
    asm("mov.b64 %0, {%1,%2};" : "=l"(v) : "f"(lo), "f"(hi));
    return v;
}
__device__ __forceinline__ void ffma2(unsigned long long& d,
                                      unsigned long long a,
                                      unsigned long long b) {
    asm("fma.rn.f32x2 %0, %1, %2, %0;" : "+l"(d) : "l"(a), "l"(b));
}
__device__ __forceinline__ unsigned long long fadd2(unsigned long long a,
                                                    unsigned long long b) {
    unsigned long long d;
    asm("add.rn.f32x2 %0, %1, %2;" : "=l"(d) : "l"(a), "l"(b));
    return d;
}
__device__ __forceinline__ float lo32(unsigned long long v) {
    return __uint_as_float((unsigned)(v & 0xffffffffu));
}
__device__ __forceinline__ float hi32(unsigned long long v) {
    return __uint_as_float((unsigned)(v >> 32));
}
__device__ __forceinline__ uint32_t smem_u32(const void* p) {
    uint32_t a;
    asm("{ .reg .u64 t; cvta.to.shared.u64 t, %1; cvt.u32.u64 %0, t; }"
        : "=r"(a) : "l"(p));
    return a;
}
__device__ __forceinline__ uint32_t mapa_rank(uint32_t laddr, uint32_t rank) {
    uint32_t ra;
    asm("mapa.shared::cluster.u32 %0, %1, %2;" : "=r"(ra) : "r"(laddr), "r"(rank));
    return ra;
}
__device__ __forceinline__ void dsmem_st128(uint32_t raddr, float4 v) {
    asm volatile("st.shared::cluster.v4.f32 [%0], {%1,%2,%3,%4};"
                 :: "r"(raddr), "f"(v.x), "f"(v.y), "f"(v.z), "f"(v.w)
                 : "memory");
}
__device__ __forceinline__ void cluster_sync() {
    asm volatile("barrier.cluster.arrive.aligned;" ::: "memory");
    asm volatile("barrier.cluster.wait.aligned;" ::: "memory");
}

extern "C" __global__ void __launch_bounds__(TPB, 1) __cluster_dims__(CL, 1, 1)
rnn_main(const float* __restrict__ input, const float* __restrict__ noise,
         const float* __restrict__ wi, const float* __restrict__ si,
         const float* __restrict__ wrec, const float* __restrict__ bias,
         const float* __restrict__ wi_mask, const float* __restrict__ wrec_mask,
         const float* __restrict__ h0, float* __restrict__ traj)
{
    // operand buffer: relu(h) for k<512, x_t for k>=512; double buffered (18 KB)
    __shared__ __align__(16) float s_op[2][NB][KTOT];
    // k-slice partial sums (16 KB)
    __shared__ __align__(16) unsigned long long s_red[NB][KS][NC];
    // relu(h_new) staging for vectorized cluster send (1 KB)
    __shared__ __align__(16) float4 s_hvec[NB][NC / 4];

    const int tid  = threadIdx.x;
    const int rank = blockIdx.x % CL;     // column tile
    const int bg   = blockIdx.x / CL;     // batch group
    const int C0   = rank * NC;           // first global column of this CTA
    const int B0   = bg * NB;             // first batch of this cluster

    // compute-role: 64 column-threads (1 col each) x 8 k-slices
    const int ct   = tid & 63;            // column-thread
    const int ksub = tid >> 6;            // k-slice [0,8)  (constant per warp)
    const int cc   = C0 + ct;             // my global column
    const int kb   = ksub * (H_ / KS);    // 64 wrec k's start
    const int ib   = ksub * (I_ / KS);    // 8 wi k's start

    // finalize-role (tid < 256): (batch, col) pairs
    const int fb = tid >> 6;              // batch within group [0,4)
    const int fc = tid & 63;              // column within tile [0,64)
    const int gb = B0 + fb;               // global batch
    const int gc = C0 + fc;               // global column

    // -------- preload effective weights, packed by (k,k+1), one column -----
    unsigned long long w2[NPAIR];         // 72 registers
#pragma unroll
    for (int p = 0; p < 32; p++) {
        int k0 = kb + 2 * p;
        float a = fabsf(wrec[(size_t)k0 * H_ + cc]) * wrec_mask[(size_t)k0 * H_ + cc];
        float b = fabsf(wrec[(size_t)(k0 + 1) * H_ + cc]) * wrec_mask[(size_t)(k0 + 1) * H_ + cc];
        w2[p] = pk2(a, b);
    }
#pragma unroll
    for (int p = 32; p < NPAIR; p++) {
        int i0 = ib + 2 * (p - 32);
        float a = wi[(size_t)i0 * H_ + cc] * si[i0] * wi_mask[(size_t)i0 * H_ + cc];
        float b = wi[(size_t)(i0 + 1) * H_ + cc] * si[i0 + 1] * wi_mask[(size_t)(i0 + 1) * H_ + cc];
        w2[p] = pk2(a, b);
    }

    // precompute peer smem bases (mapa hoisted out of the time loop)
    const uint32_t s_op_u32 = smem_u32(&s_op[0][0][0]);
    uint32_t peer_base[CL];
#pragma unroll
    for (int r = 0; r < CL; r++) peer_base[r] = mapa_rank(s_op_u32, (uint32_t)r);

    // sender-role (tid < 64): batch sb, column quad sq
    const int sb = tid >> 4;              // [0,4)
    const int sq = tid & 15;              // [0,16)
    const uint32_t send_off0 = (uint32_t)(((0 * NB + sb) * KTOT + C0 + 4 * sq) * 4);
    const uint32_t send_off1 = (uint32_t)(((1 * NB + sb) * KTOT + C0 + 4 * sq) * 4);

    const float fbias = (tid < 256) ? bias[gc] : 0.f;

    // incremented pointers (avoid per-step 64-bit address math)
    const float* nz_p = noise + ((size_t)gb * T_) * H_ + gc;           // += H_
    const float* x_p  = input + ((size_t)(B0 + (tid >> 5 & 3)) * T_) * I_
                              + ((tid & 31) * 2);                       // += I_
    float*       tr_p = traj + ((size_t)gb * (T_ + 1)) * H_ + gc;      // += H_

    // -------- init: h(0)=h0; stage relu(h0) and x_0 ------------------------
    float h_prev = 0.f;
    if (tid < 256) {
        h_prev = h0[gc];
        *tr_p = h_prev;
        tr_p += H_;
    }
#pragma unroll
    for (int q = 0; q < 4; q++) {
        int idx = tid * 4 + q;            // [0, 2048): b = idx>>9, k = idx&511
        s_op[0][idx >> 9][idx & 511] = fmaxf(h0[idx & 511], 0.f);
    }
    if (tid < 128) {
        float2 xv = *(const float2*)x_p;
        s_op[0][tid >> 5][H_ + (tid & 31) * 2] = xv.x;
        s_op[0][tid >> 5][H_ + (tid & 31) * 2 + 1] = xv.y;
        x_p += I_;
    }
    __syncthreads();

    int p = 0;
    for (int t = 0; t < T_; t++) {
        // ---- early loads (consumed ~1.5K cycles later) --------------------
        float nz = 0.f;
        if (tid < 256) { nz = *nz_p; nz_p += H_; }
        float2 xnext = make_float2(0.f, 0.f);
        if (tid < 128 && t + 1 < T_) { xnext = *(const float2*)x_p; x_p += I_; }

        // ---- matmul: acc[b] over 72 k (packed (k,k+1) pairs), 1 column ----
        unsigned long long acc[NB];
#pragma unroll
        for (int b = 0; b < NB; b++) acc[b] = 0ULL;

#pragma unroll
        for (int j2 = 0; j2 < 18; j2++) {
            const int off = (j2 < 16) ? (kb + 4 * j2) : (H_ + ib + 4 * (j2 - 16));
#pragma unroll
            for (int b = 0; b < NB; b++) {
                ulonglong2 v = *(const ulonglong2*)&s_op[p][b][off];
                ffma2(acc[b], v.x, w2[2 * j2]);
                ffma2(acc[b], v.y, w2[2 * j2 + 1]);
            }
        }

        // ---- k-slice reduction through smem -------------------------------
#pragma unroll
        for (int b = 0; b < NB; b++) s_red[b][ksub][ct] = acc[b];
        __syncthreads();

        const int pn = p ^ 1;
        // stage x_{t+1} into next buffer (local; safe: peers only write h-region)
        if (tid < 128) {
            s_op[pn][tid >> 5][H_ + (tid & 31) * 2] = xnext.x;
            s_op[pn][tid >> 5][H_ + (tid & 31) * 2 + 1] = xnext.y;
        }

        if (tid < 256) {
            unsigned long long r0 = s_red[fb][0][fc], r1 = s_red[fb][1][fc];
            unsigned long long r2 = s_red[fb][2][fc], r3 = s_red[fb][3][fc];
            unsigned long long r4 = s_red[fb][4][fc], r5 = s_red[fb][5][fc];
            unsigned long long r6 = s_red[fb][6][fc], r7 = s_red[fb][7][fc];
            unsigned long long ss = fadd2(fadd2(fadd2(r0, r1), fadd2(r2, r3)),
                                          fadd2(fadd2(r4, r5), fadd2(r6, r7)));
            float sum = lo32(ss) + hi32(ss);

            float h_new = h_prev + NSTD * nz + ALPHA * (-h_prev + sum + fbias);
            *tr_p = h_new;
            tr_p += H_;
            h_prev = h_new;
            ((float*)s_hvec)[fb * NC + fc] = fmaxf(h_new, 0.f);
        }
        __syncthreads();

        // ---- vectorized relu(h) broadcast to all cluster CTAs -------------
        if (tid < 64) {
            float4 v = s_hvec[sb][sq];
            uint32_t off = pn ? send_off1 : send_off0;
#pragma unroll
            for (int r = 0; r < CL; r++) dsmem_st128(peer_base[r] + off, v);
        }

        cluster_sync();
        p = pn;
    }
}

// output pass: out[b,t,o] = relu(traj[b,t+1,:]) @ wo_eff
extern "C" __global__ void __launch_bounds__(256)
rnn_out(const float* __restrict__ traj, const float* __restrict__ wo,
        const float* __restrict__ so, const float* __restrict__ wo_mask,
        float* __restrict__ out)
{
    __shared__ float s_wo[O_][H_];
    const int tid = threadIdx.x;
    for (int i = tid; i < H_ * O_; i += 256) {
        int c = i / O_, o = i % O_;
        s_wo[o][c] = wo[i] * so[o] * wo_mask[i];
    }
    __syncthreads();

    const int warp = tid >> 5, lane = tid & 31;
    const size_t row = (size_t)blockIdx.x * 8 + warp;   // b*T + t
    const int b = (int)(row >> 10);
    const int t = (int)(row & 1023);
    const float* tp = traj + ((size_t)b * (T_ + 1) + t + 1) * H_;

    float acc[O_];
#pragma unroll
    for (int o = 0; o < O_; o++) acc[o] = 0.f;

    for (int ccb = 0; ccb < H_; ccb += 32) {
        float r = fmaxf(tp[ccb + lane], 0.f);
#pragma unroll
        for (int o = 0; o < O_; o++) acc[o] += r * s_wo[o][ccb + lane];
    }
#pragma unroll
    for (int off = 16; off; off >>= 1)
#pragma unroll
        for (int o = 0; o < O_; o++)
            acc[o] += __shfl_down_sync(0xffffffffu, acc[o], off);
    if (lane == 0) {
#pragma unroll
        for (int o = 0; o < O_; o++) out[row * O_ + o] = acc[o];
    }
}

extern "C" void kernel_launch(void* const* d_in, const int* in_sizes, int n_in,
                              void* d_out, int out_size)
{
    (void)in_sizes; (void)n_in; (void)out_size;
    const float* input = (const float*)d_in[0];
    const float* noise = (const float*)d_in[1];
    const float* wi    = (const float*)d_in[2];
    const float* si    = (const float*)d_in[3];
    const float* wrec  = (const float*)d_in[4];
    const float* bias  = (const float*)d_in[5];
    const float* wo    = (const float*)d_in[6];
    const float* so    = (const float*)d_in[7];
    const float* wim   = (const float*)d_in[8];
    const float* wrm   = (const float*)d_in[9];
    const float* wom   = (const float*)d_in[10];
    const float* h0    = (const float*)d_in[11];

    float* out  = (float*)d_out;
    float* traj = out + (size_t)B_ * T_ * O_;   // [B, T+1, H] after [B, T, O]

    rnn_main<<<GRID, TPB>>>(input, noise, wi, si, wrec, bias,
                            wim, wrm, h0, traj);
    rnn_out<<<(B_ * T_) / 8, 256>>>(traj, wo, so, wom, out);
}

// round 4
// speedup vs baseline: 1.2738x; 1.2738x over previous
#include <cuda_runtime.h>
#include <cstdint>

#define B_   64
#define T_   1024
#define H_   512
#define I_   64
#define O_   8
#define ALPHA 0.2f
#define NSTD  0.05f

#define CL    8                 // cluster size (column tiles per batch group)
#define NBG   16                // batch groups (clusters)
#define GRID  (CL*NBG)          // 128 CTAs, single wave
#define TPB   512
#define NB    4                 // batches per cluster
#define NC    64                // columns per CTA
#define KTOT  (H_+I_)           // 576
#define KS    8                 // k-slices
#define NPAIR 36                // k-pairs per thread: (64 wrec + 8 wi)/2
#define HBYTES 8192             // bytes of h arriving per CTA per step

// ---- packed f32x2 helpers (sm_100+) ----
__device__ __forceinline__ unsigned long long pk2(float lo, float hi) {
    unsigned long long v;
    asm("mov.b64 %0, {%1,%2};" : "=l"(v) : "f"(lo), "f"(hi));
    return v;
}
__device__ __forceinline__ void ffma2(unsigned long long& d,
                                      unsigned long long a,
                                      unsigned long long b) {
    asm("fma.rn.f32x2 %0, %1, %2, %0;" : "+l"(d) : "l"(a), "l"(b));
}
__device__ __forceinline__ unsigned long long fadd2(unsigned long long a,
                                                    unsigned long long b) {
    unsigned long long d;
    asm("add.rn.f32x2 %0, %1, %2;" : "=l"(d) : "l"(a), "l"(b));
    return d;
}
__device__ __forceinline__ float lo32(unsigned long long v) {
    return __uint_as_float((unsigned)(v & 0xffffffffu));
}
__device__ __forceinline__ float hi32(unsigned long long v) {
    return __uint_as_float((unsigned)(v >> 32));
}
__device__ __forceinline__ uint32_t smem_u32(const void* p) {
    uint32_t a;
    asm("{ .reg .u64 t; cvta.to.shared.u64 t, %1; cvt.u32.u64 %0, t; }"
        : "=r"(a) : "l"(p));
    return a;
}
__device__ __forceinline__ uint32_t mapa_rank(uint32_t laddr, uint32_t rank) {
    uint32_t ra;
    asm("mapa.shared::cluster.u32 %0, %1, %2;" : "=r"(ra) : "r"(laddr), "r"(rank));
    return ra;
}
// async remote store: data + complete_tx(8) on the remote CTA's mbarrier
__device__ __forceinline__ void st_async_b64(uint32_t raddr, unsigned long long v,
                                             uint32_t rmbar) {
    asm volatile(
        "st.async.shared::cluster.mbarrier::complete_tx::bytes.b64 [%0], %1, [%2];"
        :: "r"(raddr), "l"(v), "r"(rmbar) : "memory");
}
__device__ __forceinline__ void mbar_init(uint32_t mbar, uint32_t cnt) {
    asm volatile("mbarrier.init.shared.b64 [%0], %1;" :: "r"(mbar), "r"(cnt) : "memory");
}
__device__ __forceinline__ void mbar_expect_tx(uint32_t mbar, uint32_t bytes) {
    asm volatile("mbarrier.arrive.expect_tx.shared.b64 _, [%0], %1;"
                 :: "r"(mbar), "r"(bytes) : "memory");
}
__device__ __forceinline__ void mbar_wait(uint32_t mbar, uint32_t parity) {
    uint32_t done;
    asm volatile(
        "{ .reg .pred P;\n"
        "  mbarrier.try_wait.parity.acquire.cta.shared::cta.b64 P, [%1], %2;\n"
        "  selp.b32 %0, 1, 0, P; }"
        : "=r"(done) : "r"(mbar), "r"(parity) : "memory");
    if (!done) {
        asm volatile(
            "{ .reg .pred P;\n"
            "WL%=:\n"
            "  mbarrier.try_wait.parity.acquire.cta.shared::cta.b64 P, [%0], %1, 0x989680;\n"
            "  @P bra WD%=;\n"
            "  bra WL%=;\n"
            "WD%=: }"
            :: "r"(mbar), "r"(parity) : "memory");
    }
}
__device__ __forceinline__ void cluster_sync() {
    asm volatile("barrier.cluster.arrive.aligned;" ::: "memory");
    asm volatile("barrier.cluster.wait.aligned;" ::: "memory");
}

// profiling alignment: 5 no-op launches so ncu's "-s 5 -c 1" lands on rnn_main
extern "C" __global__ void knop() {}

extern "C" __global__ void __launch_bounds__(TPB, 1) __cluster_dims__(CL, 1, 1)
rnn_main(const float* __restrict__ input, const float* __restrict__ noise,
         const float* __restrict__ wi, const float* __restrict__ si,
         const float* __restrict__ wrec, const float* __restrict__ bias,
         const float* __restrict__ wi_mask, const float* __restrict__ wrec_mask,
         const float* __restrict__ h0, float* __restrict__ traj)
{
    // operand buffer: relu(h) for k<512, x_t for k>=512; double buffered (18 KB)
    __shared__ __align__(16) float s_op[2][NB][KTOT];
    // k-slice partial sums (16 KB)
    __shared__ __align__(16) unsigned long long s_red[NB][KS][NC];
    // per-buffer arrival barriers
    __shared__ __align__(8) unsigned long long s_mbar[2];

    const int tid  = threadIdx.x;
    const int rank = blockIdx.x % CL;     // column tile
    const int bg   = blockIdx.x / CL;     // batch group
    const int C0   = rank * NC;           // first global column of this CTA
    const int B0   = bg * NB;             // first batch of this cluster

    // compute-role: 64 column-threads (1 col each) x 8 k-slices
    const int ct   = tid & 63;            // column-thread
    const int ksub = tid >> 6;            // k-slice [0,8), constant per warp
    const int cc   = C0 + ct;             // my global column
    const int kb   = ksub * (H_ / KS);    // 64 wrec k's start
    const int ib   = ksub * (I_ / KS);    // 8 wi k's start

    // finalize-role (tid < 256): (batch, col) pairs
    const int fb = tid >> 6;              // batch within group [0,4)
    const int fc = tid & 63;              // column within tile [0,64)
    const int gb = B0 + fb;               // global batch
    const int gc = C0 + fc;               // global column

    // -------- preload effective weights, packed by (k,k+1), one column -----
    unsigned long long w2[NPAIR];         // 72 registers
#pragma unroll
    for (int p = 0; p < 32; p++) {
        int k0 = kb + 2 * p;
        float a = fabsf(wrec[(size_t)k0 * H_ + cc]) * wrec_mask[(size_t)k0 * H_ + cc];
        float b = fabsf(wrec[(size_t)(k0 + 1) * H_ + cc]) * wrec_mask[(size_t)(k0 + 1) * H_ + cc];
        w2[p] = pk2(a, b);
    }
#pragma unroll
    for (int p = 32; p < NPAIR; p++) {
        int i0 = ib + 2 * (p - 32);
        float a = wi[(size_t)i0 * H_ + cc] * si[i0] * wi_mask[(size_t)i0 * H_ + cc];
        float b = wi[(size_t)(i0 + 1) * H_ + cc] * si[i0 + 1] * wi_mask[(size_t)(i0 + 1) * H_ + cc];
        w2[p] = pk2(a, b);
    }

    const uint32_t s_op_u32  = smem_u32(&s_op[0][0][0]);
    const uint32_t mbar_u32  = smem_u32(&s_mbar[0]);
    // my h-pair destination offset inside every CTA's s_op (even fc threads)
    const uint32_t dst_off0 = (uint32_t)(((0 * NB + fb) * KTOT + gc) * 4);
    const uint32_t dst_off1 = (uint32_t)(((1 * NB + fb) * KTOT + gc) * 4);

    const float fbias = (tid < 256) ? bias[gc] : 0.f;

    // incremented pointers
    const float* nz_p = noise + ((size_t)gb * T_) * H_ + gc;           // += H_
    const float* x_p  = input + ((size_t)(B0 + ((tid >> 5) & 3)) * T_) * I_
                              + ((tid & 31) * 2);                       // += I_
    float*       tr_p = traj + ((size_t)gb * (T_ + 1)) * H_ + gc;      // += H_

    // -------- init: mbarriers, h(0)=h0, stage relu(h0) and x_0 -------------
    if (tid == 0) {
        mbar_init(mbar_u32,     1u);      // buffer 0 barrier (count=1: the expect_tx)
        mbar_init(mbar_u32 + 8, 1u);      // buffer 1 barrier
    }
    float h_prev = 0.f;
    if (tid < 256) {
        h_prev = h0[gc];
        *tr_p = h_prev;
        tr_p += H_;
    }
#pragma unroll
    for (int q = 0; q < 4; q++) {
        int idx = tid * 4 + q;            // [0, 2048): b = idx>>9, k = idx&511
        s_op[0][idx >> 9][idx & 511] = fmaxf(h0[idx & 511], 0.f);
    }
    if (tid < 128) {
        float2 xv = *(const float2*)x_p;
        s_op[0][tid >> 5][H_ + (tid & 31) * 2] = xv.x;
        s_op[0][tid >> 5][H_ + (tid & 31) * 2 + 1] = xv.y;
        x_p += I_;
    }
    __syncthreads();
    cluster_sync();   // mbarriers + buffer0 visible cluster-wide before any st.async

    int p = 0;
    int ph0 = 0, ph1 = 0;
    for (int t = 0; t < T_; t++) {
        // ---- prefetch (independent of the incoming buffer) ----------------
        float nz = 0.f;
        if (tid < 256) { nz = *nz_p; nz_p += H_; }
        float2 xnext = make_float2(0.f, 0.f);
        if (tid < 128 && t + 1 < T_) { xnext = *(const float2*)x_p; x_p += I_; }

        // ---- wait for this step's operand buffer (dataflow sync) ----------
        if (t > 0) {
            if (p == 0) { mbar_wait(mbar_u32, ph0);     ph0 ^= 1; }
            else        { mbar_wait(mbar_u32 + 8, ph1); ph1 ^= 1; }
        }
        const int pn = p ^ 1;
        // post expectation for the buffer written during this step
        if (tid == 0 && t + 1 < T_)
            mbar_expect_tx(mbar_u32 + 8 * pn, HBYTES);

        // ---- matmul: acc[b] over 72 k (packed (k,k+1) pairs), 1 column ----
        unsigned long long acc[NB];
#pragma unroll
        for (int b = 0; b < NB; b++) acc[b] = 0ULL;

#pragma unroll
        for (int j2 = 0; j2 < 18; j2++) {
            const int off = (j2 < 16) ? (kb + 4 * j2) : (H_ + ib + 4 * (j2 - 16));
#pragma unroll
            for (int b = 0; b < NB; b++) {
                ulonglong2 v = *(const ulonglong2*)&s_op[p][b][off];
                ffma2(acc[b], v.x, w2[2 * j2]);
                ffma2(acc[b], v.y, w2[2 * j2 + 1]);
            }
        }

        // ---- k-slice reduction through smem -------------------------------
#pragma unroll
        for (int b = 0; b < NB; b++) s_red[b][ksub][ct] = acc[b];
        __syncthreads();                  // bar1: partials ready

        if (tid < 256) {
            unsigned long long r0 = s_red[fb][0][fc], r1 = s_red[fb][1][fc];
            unsigned long long r2 = s_red[fb][2][fc], r3 = s_red[fb][3][fc];
            unsigned long long r4 = s_red[fb][4][fc], r5 = s_red[fb][5][fc];
            unsigned long long r6 = s_red[fb][6][fc], r7 = s_red[fb][7][fc];
            unsigned long long ss = fadd2(fadd2(fadd2(r0, r1), fadd2(r2, r3)),
                                          fadd2(fadd2(r4, r5), fadd2(r6, r7)));
            float sum = lo32(ss) + hi32(ss);

            float h_new = h_prev + NSTD * nz + ALPHA * (-h_prev + sum + fbias);
            float rv = fmaxf(h_new, 0.f);
            // pair with odd neighbor for 8-byte async sends (full warps 0-7)
            float rv_hi = __shfl_down_sync(0xffffffffu, rv, 1);

            if (((fc & 1) == 0) && (t + 1 < T_)) {
                unsigned long long hv = pk2(rv, rv_hi);
                uint32_t doff = pn ? dst_off1 : dst_off0;
                uint32_t moff = mbar_u32 + 8 * pn;
#pragma unroll
                for (int r = 0; r < CL; r++) {
                    uint32_t ra = mapa_rank(s_op_u32 + doff, (uint32_t)r);
                    uint32_t rm = mapa_rank(moff, (uint32_t)r);
                    st_async_b64(ra, hv, rm);
                }
            }

            // off the critical path: trajectory store + state update
            *tr_p = h_new;
            tr_p += H_;
            h_prev = h_new;
        }

        // stage x_{t+1} into next buffer (local region, disjoint from h)
        if (tid < 128) {
            s_op[pn][tid >> 5][H_ + (tid & 31) * 2] = xnext.x;
            s_op[pn][tid >> 5][H_ + (tid & 31) * 2 + 1] = xnext.y;
        }

        __syncthreads();                  // bar2: s_red reuse + x staging visible
        p = pn;
    }

    cluster_sync();   // no CTA exits while peers' st.async may still target it
}

// output pass: out[b,t,o] = relu(traj[b,t+1,:]) @ wo_eff
extern "C" __global__ void __launch_bounds__(256)
rnn_out(const float* __restrict__ traj, const float* __restrict__ wo,
        const float* __restrict__ so, const float* __restrict__ wo_mask,
        float* __restrict__ out)
{
    __shared__ float s_wo[O_][H_];
    const int tid = threadIdx.x;
    for (int i = tid; i < H_ * O_; i += 256) {
        int c = i / O_, o = i % O_;
        s_wo[o][c] = wo[i] * so[o] * wo_mask[i];
    }
    __syncthreads();

    const int warp = tid >> 5, lane = tid & 31;
    const size_t row = (size_t)blockIdx.x * 8 + warp;   // b*T + t
    const int b = (int)(row >> 10);
    const int t = (int)(row & 1023);
    const float* tp = traj + ((size_t)b * (T_ + 1) + t + 1) * H_;

    float acc[O_];
#pragma unroll
    for (int o = 0; o < O_; o++) acc[o] = 0.f;

    for (int ccb = 0; ccb < H_; ccb += 32) {
        float r = fmaxf(tp[ccb + lane], 0.f);
#pragma unroll
        for (int o = 0; o < O_; o++) acc[o] += r * s_wo[o][ccb + lane];
    }
#pragma unroll
    for (int off = 16; off; off >>= 1)
#pragma unroll
        for (int o = 0; o < O_; o++)
            acc[o] += __shfl_down_sync(0xffffffffu, acc[o], off);
    if (lane == 0) {
#pragma unroll
        for (int o = 0; o < O_; o++) out[row * O_ + o] = acc[o];
    }
}

extern "C" void kernel_launch(void* const* d_in, const int* in_sizes, int n_in,
                              void* d_out, int out_size)
{
    (void)in_sizes; (void)n_in; (void)out_size;
    const float* input = (const float*)d_in[0];
    const float* noise = (const float*)d_in[1];
    const float* wi    = (const float*)d_in[2];
    const float* si    = (const float*)d_in[3];
    const float* wrec  = (const float*)d_in[4];
    const float* bias  = (const float*)d_in[5];
    const float* wo    = (const float*)d_in[6];
    const float* so    = (const float*)d_in[7];
    const float* wim   = (const float*)d_in[8];
    const float* wrm   = (const float*)d_in[9];
    const float* wom   = (const float*)d_in[10];
    const float* h0    = (const float*)d_in[11];

    float* out  = (float*)d_out;
    float* traj = out + (size_t)B_ * T_ * O_;   // [B, T+1, H] after [B, T, O]

    // 5 no-op launches: aligns ncu's "-s 5 -c 1" capture onto rnn_main
    for (int i = 0; i < 5; i++) knop<<<1, 32>>>();

    rnn_main<<<GRID, TPB>>>(input, noise, wi, si, wrec, bias,
                            wim, wrm, h0, traj);
    rnn_out<<<(B_ * T_) / 8, 256>>>(traj, wo, so, wom, out);
}